// round 5
// baseline (speedup 1.0000x reference)
#include <cuda_runtime.h>
#include <math_constants.h>

// Problem constants (fixed by the reference):
//   outputs: (B, C) fp32, targets: (B,) i32, ages: (B,) i32, weight: (C,) fp32
//   T = 2.0 softmax temperature; output = scalar fp32 mean loss.
//
// Math: soft_targets has exactly two nonzeros (t, t+1), so
//   per_row = -[(1-d)*w[t]*(x[t]/T - lse) + d*w[t+1]*(x[t+1]/T - lse)]
//
// KEY STRUCTURE (R4 lesson): the two-pass max-then-exp over the register-
// resident row is what FORCES ptxas to issue all 8 LDG.128 back-to-back
// (every element is live for the max) -> MLP_p1=8 -> 5.6 TB/s (R1 evidence).
// Single-pass variants get re-interleaved by ptxas (regs=32, 4.9 TB/s).
#define B_ROWS 32768
#define C_COLS 1024
#define ROWS_PER_BLOCK 8
#define THREADS (ROWS_PER_BLOCK * 32)
#define NBLOCKS (B_ROWS / ROWS_PER_BLOCK) // 4096

// Scratch for deterministic single-launch reduction (no cudaMalloc allowed).
__device__ float g_partials[NBLOCKS];
__device__ unsigned int g_count = 0;

__global__ __launch_bounds__(THREADS)
void loss_fused_kernel(const float* __restrict__ outputs,
                       const int*   __restrict__ targets,
                       const int*   __restrict__ ages,
                       const float* __restrict__ weight,
                       float*       __restrict__ out) {
    const int warp = threadIdx.x >> 5;
    const int lane = threadIdx.x & 31;
    const int row  = blockIdx.x * ROWS_PER_BLOCK + warp;

    const float4* rp = reinterpret_cast<const float4*>(
        outputs + (size_t)row * C_COLS);

    // Load full row into registers (all values live across the max pass ->
    // ptxas must front-batch all 8 LDG.128).
    float4 v[8];
#pragma unroll
    for (int k = 0; k < 8; ++k) v[k] = rp[k * 32 + lane];

    // Pass 1: scale by 1/T and per-lane max (4 parallel max chains).
    float m0 = -CUDART_INF_F, m1 = -CUDART_INF_F;
    float m2 = -CUDART_INF_F, m3 = -CUDART_INF_F;
#pragma unroll
    for (int k = 0; k < 8; ++k) {
        v[k].x *= 0.5f; v[k].y *= 0.5f; v[k].z *= 0.5f; v[k].w *= 0.5f;
        m0 = fmaxf(m0, v[k].x); m1 = fmaxf(m1, v[k].y);
        m2 = fmaxf(m2, v[k].z); m3 = fmaxf(m3, v[k].w);
    }
    float m = fmaxf(fmaxf(m0, m1), fmaxf(m2, m3));
#pragma unroll
    for (int off = 16; off > 0; off >>= 1)
        m = fmaxf(m, __shfl_xor_sync(0xFFFFFFFFu, m, off));

    // Pass 2: exp-sum with 4 parallel accumulators.
    float s0 = 0.0f, s1 = 0.0f, s2 = 0.0f, s3 = 0.0f;
#pragma unroll
    for (int k = 0; k < 8; ++k) {
        s0 += __expf(v[k].x - m);
        s1 += __expf(v[k].y - m);
        s2 += __expf(v[k].z - m);
        s3 += __expf(v[k].w - m);
    }
    float s = (s0 + s1) + (s2 + s3);
#pragma unroll
    for (int off = 16; off > 0; off >>= 1)
        s += __shfl_xor_sync(0xFFFFFFFFu, s, off);

    __shared__ float sh[ROWS_PER_BLOCK];
    if (lane == 0) {
        const float lse = m + __logf(s);
        const int   t    = targets[row];
        const float agef = (float)ages[row];
        const float delta = (agef > 50.0f && agef < 60.0f)
                                ? (agef - 50.0f) * 0.1f : 0.0f;
        // Re-reads of this row hit L1 (the warp just loaded those lines).
        const float yt  = outputs[(size_t)row * C_COLS + t]     * 0.5f;
        const float yt1 = outputs[(size_t)row * C_COLS + t + 1] * 0.5f;
        const float loss = -((1.0f - delta) * weight[t]     * (yt  - lse)
                           +         delta  * weight[t + 1] * (yt1 - lse));
        sh[warp] = loss;
    }
    __syncthreads();

    __shared__ bool s_last;
    if (threadIdx.x == 0) {
        float p = 0.0f;
#pragma unroll
        for (int i = 0; i < ROWS_PER_BLOCK; ++i) p += sh[i];
        g_partials[blockIdx.x] = p;
        __threadfence();
        const unsigned int prev = atomicAdd(&g_count, 1u);
        s_last = (prev == (unsigned int)(NBLOCKS - 1));
    }
    __syncthreads();

    if (!s_last) return;

    // Final reduce: this block reads all partials in a FIXED order
    // (deterministic output across replays).
    {
        const int tid = threadIdx.x;
        float acc = 0.0f;
#pragma unroll
        for (int i = 0; i < NBLOCKS / THREADS; ++i)
            acc += g_partials[tid + i * THREADS];

#pragma unroll
        for (int off = 16; off > 0; off >>= 1)
            acc += __shfl_xor_sync(0xFFFFFFFFu, acc, off);

        __shared__ float shw[ROWS_PER_BLOCK];
        if (lane == 0) shw[warp] = acc;
        __syncthreads();
        if (threadIdx.x == 0) {
            float total = 0.0f;
#pragma unroll
            for (int i = 0; i < ROWS_PER_BLOCK; ++i) total += shw[i];
            out[0] = total * (1.0f / (float)B_ROWS);
            g_count = 0; // reset for next graph replay
        }
    }
}

extern "C" void kernel_launch(void* const* d_in, const int* in_sizes, int n_in,
                              void* d_out, int out_size) {
    const float* outputs = (const float*)d_in[0];
    const int*   targets = (const int*)d_in[1];
    const int*   ages    = (const int*)d_in[2];
    const float* weight  = (const float*)d_in[3];
    float*       out     = (float*)d_out;

    loss_fused_kernel<<<NBLOCKS, THREADS>>>(outputs, targets, ages, weight, out);
}

// round 6
// speedup vs baseline: 1.0714x; 1.0714x over previous
#include <cuda_runtime.h>
#include <math_constants.h>

// Problem constants (fixed by the reference):
//   outputs: (B, C) fp32, targets: (B,) i32, ages: (B,) i32, weight: (C,) fp32
//   T = 2.0 softmax temperature; output = scalar fp32 mean loss.
//
// R5 finding: LDG.128 variants are bound by L1tex wavefront replay
// (4 wf/instr @ 2.07 cyc within-LDG = ~57K cyc/SM, matching all measured
// ~28.8us durations). Scalar LDG.32 = 1 wf/instr @ 1.0 cyc cross-LDG rate
// -> L1tex drops to ~7K cyc/SM and DRAM becomes the limiter (~16us floor).
#define B_ROWS 32768
#define C_COLS 1024
#define ROWS_PER_BLOCK 8
#define THREADS (ROWS_PER_BLOCK * 32)
#define NBLOCKS (B_ROWS / ROWS_PER_BLOCK) // 4096

// Scratch for deterministic two-stage reduction (no cudaMalloc allowed).
__device__ float g_partials[NBLOCKS];

// Stage 1: one warp per row, 32 scalar loads per lane (each warp-load = one
// contiguous 128B line). Two-pass max->exp keeps all 32 values live.
__global__ __launch_bounds__(THREADS)
void loss_rows_kernel(const float* __restrict__ outputs,
                      const int*   __restrict__ targets,
                      const int*   __restrict__ ages,
                      const float* __restrict__ weight) {
    const int warp = threadIdx.x >> 5;
    const int lane = threadIdx.x & 31;
    const int row  = blockIdx.x * ROWS_PER_BLOCK + warp;

    const float* rp = outputs + (size_t)row * C_COLS;

    // 32 independent scalar loads; lane l, iter k -> element k*32 + l
    // (warp covers exactly one 128B line per k). No vectorization possible
    // (per-thread stride 128B), so these stay LDG.E.32.
    float x[32];
#pragma unroll
    for (int k = 0; k < 32; ++k) x[k] = rp[k * 32 + lane];

    // Pass 1: scale by 1/T, per-lane max (4 parallel chains).
    float m0 = -CUDART_INF_F, m1 = -CUDART_INF_F;
    float m2 = -CUDART_INF_F, m3 = -CUDART_INF_F;
#pragma unroll
    for (int k = 0; k < 32; k += 4) {
        x[k + 0] *= 0.5f; x[k + 1] *= 0.5f;
        x[k + 2] *= 0.5f; x[k + 3] *= 0.5f;
        m0 = fmaxf(m0, x[k + 0]); m1 = fmaxf(m1, x[k + 1]);
        m2 = fmaxf(m2, x[k + 2]); m3 = fmaxf(m3, x[k + 3]);
    }
    float m = fmaxf(fmaxf(m0, m1), fmaxf(m2, m3));
#pragma unroll
    for (int off = 16; off > 0; off >>= 1)
        m = fmaxf(m, __shfl_xor_sync(0xFFFFFFFFu, m, off));

    // Pass 2: exp-sum with 4 parallel accumulators.
    float s0 = 0.0f, s1 = 0.0f, s2 = 0.0f, s3 = 0.0f;
#pragma unroll
    for (int k = 0; k < 32; k += 4) {
        s0 += __expf(x[k + 0] - m);
        s1 += __expf(x[k + 1] - m);
        s2 += __expf(x[k + 2] - m);
        s3 += __expf(x[k + 3] - m);
    }
    float s = (s0 + s1) + (s2 + s3);
#pragma unroll
    for (int off = 16; off > 0; off >>= 1)
        s += __shfl_xor_sync(0xFFFFFFFFu, s, off);

    __shared__ float sh[ROWS_PER_BLOCK];
    if (lane == 0) {
        const float lse = m + __logf(s);
        const int   t    = targets[row];
        const float agef = (float)ages[row];
        const float delta = (agef > 50.0f && agef < 60.0f)
                                ? (agef - 50.0f) * 0.1f : 0.0f;
        // Re-reads of this row hit L1 (the warp just loaded those lines).
        const float yt  = rp[t]     * 0.5f;
        const float yt1 = rp[t + 1] * 0.5f;
        const float loss = -((1.0f - delta) * weight[t]     * (yt  - lse)
                           +         delta  * weight[t + 1] * (yt1 - lse));
        sh[warp] = loss;
    }
    __syncthreads();
    if (threadIdx.x == 0) {
        float p = 0.0f;
#pragma unroll
        for (int i = 0; i < ROWS_PER_BLOCK; ++i) p += sh[i];
        g_partials[blockIdx.x] = p;
    }
}

// Stage 2: single-block deterministic reduce of 4096 partials -> mean.
// One float4 per thread (single load round), then two shuffle trees.
__global__ __launch_bounds__(1024)
void reduce_kernel(float* __restrict__ out) {
    const int tid  = threadIdx.x;
    const int lane = tid & 31;
    const int warp = tid >> 5;

    const float4 v = reinterpret_cast<const float4*>(g_partials)[tid];
    float s = (v.x + v.y) + (v.z + v.w);

#pragma unroll
    for (int off = 16; off > 0; off >>= 1)
        s += __shfl_xor_sync(0xFFFFFFFFu, s, off);

    __shared__ float sh[32];
    if (lane == 0) sh[warp] = s;
    __syncthreads();
    if (warp == 0) {
        float t = sh[lane];
#pragma unroll
        for (int off = 16; off > 0; off >>= 1)
            t += __shfl_xor_sync(0xFFFFFFFFu, t, off);
        if (lane == 0) out[0] = t * (1.0f / (float)B_ROWS);
    }
}

extern "C" void kernel_launch(void* const* d_in, const int* in_sizes, int n_in,
                              void* d_out, int out_size) {
    const float* outputs = (const float*)d_in[0];
    const int*   targets = (const int*)d_in[1];
    const int*   ages    = (const int*)d_in[2];
    const float* weight  = (const float*)d_in[3];
    float*       out     = (float*)d_out;

    loss_rows_kernel<<<NBLOCKS, THREADS>>>(outputs, targets, ages, weight);
    reduce_kernel<<<1, 1024>>>(out);
}